// round 10
// baseline (speedup 1.0000x reference)
#include <cuda_runtime.h>
#include <cuda_bf16.h>
#include <stdint.h>

#define BATCH 2048
#define HW81  81
#define CDIM  512
#define HID   256
#define MROWS (BATCH * HW81)   /* 165888 */

#define NCHUNK   4
#define BCHUNK   (BATCH / NCHUNK)          /* 512 batches */
#define RCHUNK   (BCHUNK * HW81)           /* 41472 rows  */

// Scratch: xq = x @ W^T + b, [B*81, 256] fp32 (170 MB)
__device__ float g_Y[(size_t)MROWS * HID];
// W pre-rounded to tf32 format (stored as fp32 bit patterns), [256][512]
__device__ float g_Wt[HID * CDIM];
// final attention weights P, [2048][81]
__device__ float g_P[(size_t)BATCH * HW81];

// ---------------------------------------------------------------------------
// helpers
// ---------------------------------------------------------------------------
__device__ __forceinline__ uint32_t f2tf32(float f) {
    uint32_t u;
    asm("cvt.rna.tf32.f32 %0, %1;" : "=r"(u) : "f"(f));
    return u;
}

__device__ __forceinline__ uint32_t smem_u32(const void* p) {
    uint32_t a;
    asm("{ .reg .u64 t; cvta.to.shared.u64 t, %1; cvt.u32.u64 %0, t; }" : "=r"(a) : "l"(p));
    return a;
}

__device__ __forceinline__ void cp16(uint32_t dst, const void* src) {
    asm volatile("cp.async.cg.shared.global [%0], [%1], 16;" :: "r"(dst), "l"(src));
}

__device__ __forceinline__ void mma_tf32(float* c, uint32_t a0, uint32_t a1,
                                         uint32_t a2, uint32_t a3,
                                         uint32_t b0, uint32_t b1) {
    asm volatile(
        "mma.sync.aligned.m16n8k8.row.col.f32.tf32.tf32.f32 "
        "{%0,%1,%2,%3}, {%4,%5,%6,%7}, {%8,%9}, {%0,%1,%2,%3};\n"
        : "+f"(c[0]), "+f"(c[1]), "+f"(c[2]), "+f"(c[3])
        : "r"(a0), "r"(a1), "r"(a2), "r"(a3), "r"(b0), "r"(b1));
}

// ---------------------------------------------------------------------------
// Kernel 0: round W to tf32 (RNA) once.
// ---------------------------------------------------------------------------
__global__ void wprep_kernel(const float* __restrict__ Wf) {
    int i = blockIdx.x * 512 + threadIdx.x;
    uint32_t u = f2tf32(Wf[i]);
    g_Wt[i] = __uint_as_float(u);
}

// ---------------------------------------------------------------------------
// Kernel 1: TF32 GEMM.  Y[r,n] = sum_k X[r,k]*W[n,k] + b[n]
// CTA tile 256(M) x 128(N), 512 threads = 16 warps (4M x 4N), warp tile 64x32.
// K staged 64 at a time, cp.async double-buffered.
// After each stage lands, each thread converts ITS OWN cp.async'd A chunks
// to tf32 in place (visible to self after wait_group, no extra barrier) —
// removes all cvt from the MMA inner loop (they were 8x redundant there).
// ---------------------------------------------------------------------------
#define STRIDE   68
#define OFF_A0   0
#define OFF_A1   (256 * STRIDE)              /* 17408 */
#define OFF_B0   (2 * 256 * STRIDE)          /* 34816 */
#define OFF_B1   (OFF_B0 + 128 * STRIDE)     /* 43520 */
#define SMEM_FLOATS (OFF_B1 + 128 * STRIDE)  /* 52224 floats = 208896 B */

__global__ __launch_bounds__(512, 1)
void gemm_tf32(const float* __restrict__ X, const float* __restrict__ bfc,
               int rowBase)
{
    extern __shared__ __align__(16) float smem[];

    const int tid  = threadIdx.x;
    const int lane = tid & 31;
    const int warp = tid >> 5;
    const int wm   = warp >> 2;          // 0..3 (M)
    const int wn   = warp & 3;           // 0..3 (N)
    const int row0 = rowBase + blockIdx.y * 256;
    const int col0 = blockIdx.x * 128;
    const uint32_t sbase = smem_u32(smem);

    float acc[4][4][4];
#pragma unroll
    for (int a = 0; a < 4; a++)
#pragma unroll
        for (int b = 0; b < 4; b++)
#pragma unroll
            for (int d = 0; d < 4; d++) acc[a][b][d] = 0.f;

    const float* Xc = X + (size_t)row0 * CDIM;
    const float* Wc = g_Wt + (size_t)col0 * CDIM;

#define ISSUE_STAGE(IT, OFFA, OFFB)                                          \
    do {                                                                     \
        const int k0 = (IT) * 64;                                            \
        _Pragma("unroll")                                                    \
        for (int i = 0; i < 8; i++) {                                        \
            int f = i * 512 + tid;  /* 0..4095 */                            \
            int r = f >> 4, j = (f & 15) << 2;                               \
            cp16(sbase + ((OFFA) + r * STRIDE + j) * 4,                      \
                 Xc + (size_t)r * CDIM + k0 + j);                            \
        }                                                                    \
        _Pragma("unroll")                                                    \
        for (int i = 0; i < 4; i++) {                                        \
            int f = i * 512 + tid;  /* 0..2047 */                            \
            int r = f >> 4, j = (f & 15) << 2;                               \
            cp16(sbase + ((OFFB) + r * STRIDE + j) * 4,                      \
                 Wc + (size_t)r * CDIM + k0 + j);                            \
        }                                                                    \
        asm volatile("cp.async.commit_group;" ::: "memory");                 \
    } while (0)

    // convert this thread's own A chunks (the ones it cp.async'd) in place
#define CONVERT_A(OFFA)                                                      \
    do {                                                                     \
        _Pragma("unroll")                                                    \
        for (int i = 0; i < 8; i++) {                                        \
            int f = i * 512 + tid;                                           \
            int r = f >> 4, j = (f & 15) << 2;                               \
            float4* p = (float4*)(smem + (OFFA) + r * STRIDE + j);           \
            float4 v = *p;                                                   \
            v.x = __uint_as_float(f2tf32(v.x));                              \
            v.y = __uint_as_float(f2tf32(v.y));                              \
            v.z = __uint_as_float(f2tf32(v.z));                              \
            v.w = __uint_as_float(f2tf32(v.w));                              \
            *p = v;                                                          \
        }                                                                    \
    } while (0)

    ISSUE_STAGE(0, OFF_A0, OFF_B0);
    ISSUE_STAGE(1, OFF_A1, OFF_B1);

    const int ar = wm * 64 + (lane >> 2);
    const int ac = lane & 3;
    const int bn = wn * 32 + (lane >> 2);

    for (int it = 0; it < 8; it++) {
        if (it < 7) asm volatile("cp.async.wait_group 1;" ::: "memory");
        else        asm volatile("cp.async.wait_group 0;" ::: "memory");

        // in-place A -> tf32 on own data (self-visible after wait_group)
        if (it & 1) CONVERT_A(OFF_A1);
        else        CONVERT_A(OFF_A0);

        __syncthreads();

        const uint32_t* sA = (const uint32_t*)(smem + ((it & 1) ? OFF_A1 : OFF_A0));
        const uint32_t* sB = (const uint32_t*)(smem + ((it & 1) ? OFF_B1 : OFF_B0));

#pragma unroll
        for (int kk = 0; kk < 8; kk++) {
            const int c = kk * 8 + ac;
            uint32_t b[4][2];
#pragma unroll
            for (int nt = 0; nt < 4; nt++) {
                b[nt][0] = sB[(bn + nt * 8) * STRIDE + c];
                b[nt][1] = sB[(bn + nt * 8) * STRIDE + c + 4];
            }
#pragma unroll
            for (int mt = 0; mt < 4; mt++) {
                const int r = ar + mt * 16;
                uint32_t a0 = sA[r * STRIDE + c];
                uint32_t a1 = sA[(r + 8) * STRIDE + c];
                uint32_t a2 = sA[r * STRIDE + c + 4];
                uint32_t a3 = sA[(r + 8) * STRIDE + c + 4];
#pragma unroll
                for (int nt = 0; nt < 4; nt++)
                    mma_tf32(acc[mt][nt], a0, a1, a2, a3, b[nt][0], b[nt][1]);
            }
        }
        __syncthreads();

        if (it < 6) {
            if (it & 1) ISSUE_STAGE(it + 2, OFF_A1, OFF_B1);
            else        ISSUE_STAGE(it + 2, OFF_A0, OFF_B0);
        }
    }

    // ---- epilogue: + bias, write fp32 Y ----
#pragma unroll
    for (int nt = 0; nt < 4; nt++) {
        const int c  = col0 + wn * 32 + nt * 8 + ((lane & 3) << 1);
        const float b0 = __ldg(bfc + c);
        const float b1 = __ldg(bfc + c + 1);
#pragma unroll
        for (int mt = 0; mt < 4; mt++) {
            const int r = row0 + wm * 64 + mt * 16 + (lane >> 2);
            float2 v0 = make_float2(acc[mt][nt][0] + b0, acc[mt][nt][1] + b1);
            float2 v1 = make_float2(acc[mt][nt][2] + b0, acc[mt][nt][3] + b1);
            *(float2*)&g_Y[(size_t)r * HID + c]       = v0;
            *(float2*)&g_Y[(size_t)(r + 8) * HID + c] = v1;
        }
    }
}

// ---------------------------------------------------------------------------
// Kernel 2a: syrk + double softmax.  One CTA (128 threads) per batch.
// Writes final P[b][81].
// ---------------------------------------------------------------------------
__global__ __launch_bounds__(128)
void syrk_kernel(int batch0)
{
    const int b    = batch0 + blockIdx.x;
    const int tid  = threadIdx.x;
    const int lane = tid & 31;
    const int warp = tid >> 5;

    __shared__ float sRed[4][45];
    __shared__ float sAttn[81];
    __shared__ float sB[81];

    const float* Yb = g_Y + (size_t)b * (HW81 * HID);

    float acc[45];
#pragma unroll
    for (int i = 0; i < 45; i++) acc[i] = 0.f;

#pragma unroll
    for (int cc = 0; cc < 2; cc++) {
        const int h = tid + cc * 128;
#pragma unroll
        for (int p = 0; p < 9; p++) {
            float z[9];
#pragma unroll
            for (int q = 0; q < 9; q++) {
                int rm = (3 * (q / 3) + p / 3) * 9 + 3 * (q % 3) + (p % 3);
                z[q] = Yb[rm * HID + h];
            }
            int cidx = 0;
#pragma unroll
            for (int n = 0; n < 9; n++)
#pragma unroll
                for (int m = n; m < 9; m++)
                    acc[cidx++] += z[n] * z[m];
        }
    }
#pragma unroll
    for (int i = 0; i < 45; i++) {
        float v = acc[i];
#pragma unroll
        for (int o = 16; o > 0; o >>= 1) v += __shfl_xor_sync(0xffffffffu, v, o);
        if (lane == 0) sRed[warp][i] = v;
    }
    __syncthreads();

    if (tid < 45) {
        float s = sRed[0][tid] + sRed[1][tid] + sRed[2][tid] + sRed[3][tid];
        int n = 0, m = tid;
        while (m >= 9 - n) { m -= (9 - n); n++; }
        m += n;
        float v = s * (1.0f / 48.0f);     // (hidden*P)^-0.5 = 1/sqrt(2304)
        if (n == m) v -= 100.0f;
        sAttn[n * 9 + m] = v;
        sAttn[m * 9 + n] = v;
    }
    __syncthreads();

    if (tid < 81) {
        int n = tid / 9, k = tid % 9;
        float s = 0.f;
#pragma unroll
        for (int m = 0; m < 9; m++) s += sAttn[n * 9 + m] * sAttn[k * 9 + m];
        sB[tid] = s * (1.0f / 3.0f);
    }
    __syncthreads();

    if (tid < 9) {
        int n = tid;
        float mx = -1e30f;
#pragma unroll
        for (int k = 0; k < 9; k++) mx = fmaxf(mx, sB[n * 9 + k]);
        float e[9]; float se = 0.f;
#pragma unroll
        for (int k = 0; k < 9; k++) { e[k] = expf(sB[n * 9 + k] - mx); se += e[k]; }
        float inv = 1.0f / se;
        float L[9]; float mx2 = -1e30f;
#pragma unroll
        for (int k = 0; k < 9; k++) {
            L[k] = sAttn[n * 9 + k] + e[k] * inv;
            mx2 = fmaxf(mx2, L[k]);
        }
        float e2[9]; float s2 = 0.f;
#pragma unroll
        for (int k = 0; k < 9; k++) { e2[k] = expf(L[k] - mx2); s2 += e2[k]; }
        float inv2 = 1.0f / s2;
#pragma unroll
        for (int k = 0; k < 9; k++) g_P[(size_t)b * HW81 + n * 9 + k] = e2[k] * inv2;
    }
}

// ---------------------------------------------------------------------------
// Kernel 2b: epilogue.  out[n,p,c] = sum_m P[n,m] * x[m,p,c].
// ---------------------------------------------------------------------------
__global__ __launch_bounds__(256)
void epi_kernel(const float* __restrict__ X, float* __restrict__ out, int batch0)
{
    const int b   = batch0 + blockIdx.x;
    const int tid = threadIdx.x;

    __shared__ float sP[81];
    if (tid < 81) sP[tid] = g_P[(size_t)b * HW81 + tid];
    __syncthreads();

    const float2* Xb = (const float2*)X + (size_t)b * (HW81 * 256);
    float2*       Ob = (float2*)out     + (size_t)b * (HW81 * 256);

#pragma unroll
    for (int p = 0; p < 9; p++) {
        float2 v[9];
#pragma unroll
        for (int m = 0; m < 9; m++) {
            int rm = (3 * (m / 3) + p / 3) * 9 + 3 * (m % 3) + (p % 3);
            v[m] = Xb[rm * 256 + tid];
        }
#pragma unroll
        for (int n = 0; n < 9; n++) {
            int rm = (3 * (n / 3) + p / 3) * 9 + 3 * (n % 3) + (p % 3);
            float2 o = make_float2(0.f, 0.f);
#pragma unroll
            for (int m = 0; m < 9; m++) {
                float w = sP[n * 9 + m];
                o.x += w * v[m].x;
                o.y += w * v[m].y;
            }
            Ob[rm * 256 + tid] = o;
        }
    }
}

// ---------------------------------------------------------------------------
extern "C" void kernel_launch(void* const* d_in, const int* in_sizes, int n_in,
                              void* d_out, int out_size)
{
    const float* x   = (const float*)d_in[0];   // [2048, 9, 9, 512] fp32
    const float* Wf  = (const float*)d_in[1];   // [256, 512] fp32
    const float* bfc = (const float*)d_in[2];   // [256] fp32
    float* out = (float*)d_out;

    static cudaStream_t s1 = nullptr;
    static cudaEvent_t  evG[NCHUNK], evJ;
    if (!s1) {
        cudaStreamCreateWithFlags(&s1, cudaStreamNonBlocking);
        for (int c = 0; c < NCHUNK; c++)
            cudaEventCreateWithFlags(&evG[c], cudaEventDisableTiming);
        cudaEventCreateWithFlags(&evJ, cudaEventDisableTiming);
        cudaFuncSetAttribute(gemm_tf32, cudaFuncAttributeMaxDynamicSharedMemorySize,
                             SMEM_FLOATS * 4);
    }

    // stream 0 (capture origin): wprep, then 4 gemm chunks, event after each
    wprep_kernel<<<256, 512>>>(Wf);
    for (int c = 0; c < NCHUNK; c++) {
        dim3 g1(HID / 128, RCHUNK / 256);        // (2, 162)
        gemm_tf32<<<g1, 512, SMEM_FLOATS * 4>>>(x, bfc, c * RCHUNK);
        cudaEventRecord(evG[c], 0);
    }

    // stream s1: per-chunk attention, gated on that chunk's gemm
    for (int c = 0; c < NCHUNK; c++) {
        cudaStreamWaitEvent(s1, evG[c], 0);
        syrk_kernel<<<BCHUNK, 128, 0, s1>>>(c * BCHUNK);
        epi_kernel<<<BCHUNK, 256, 0, s1>>>(x, out, c * BCHUNK);
    }

    // join back to the origin stream
    cudaEventRecord(evJ, s1);
    cudaStreamWaitEvent(0, evJ, 0);
}

// round 11
// speedup vs baseline: 1.1089x; 1.1089x over previous
#include <cuda_runtime.h>
#include <cuda_bf16.h>
#include <stdint.h>

#define BATCH 2048
#define HW81  81
#define CDIM  512
#define HID   256
#define MROWS (BATCH * HW81)   /* 165888 */

#define NCHUNK   4
#define BCHUNK   (BATCH / NCHUNK)          /* 512 batches */
#define RCHUNK   (BCHUNK * HW81)           /* 41472 rows  */

// Scratch: xq = x @ W^T + b, [B*81, 256] fp32 (170 MB)
__device__ float g_Y[(size_t)MROWS * HID];
// W pre-rounded to tf32 format (stored as fp32 bit patterns), [256][512]
__device__ float g_Wt[HID * CDIM];
// final attention weights P, [2048][81]
__device__ float g_P[(size_t)BATCH * HW81];

// ---------------------------------------------------------------------------
// helpers
// ---------------------------------------------------------------------------
__device__ __forceinline__ uint32_t f2tf32(float f) {
    uint32_t u;
    asm("cvt.rna.tf32.f32 %0, %1;" : "=r"(u) : "f"(f));
    return u;
}

__device__ __forceinline__ uint32_t smem_u32(const void* p) {
    uint32_t a;
    asm("{ .reg .u64 t; cvta.to.shared.u64 t, %1; cvt.u32.u64 %0, t; }" : "=r"(a) : "l"(p));
    return a;
}

__device__ __forceinline__ void cp16(uint32_t dst, const void* src) {
    asm volatile("cp.async.cg.shared.global [%0], [%1], 16;" :: "r"(dst), "l"(src));
}

__device__ __forceinline__ void mma_tf32(float* c, uint32_t a0, uint32_t a1,
                                         uint32_t a2, uint32_t a3,
                                         uint32_t b0, uint32_t b1) {
    asm volatile(
        "mma.sync.aligned.m16n8k8.row.col.f32.tf32.tf32.f32 "
        "{%0,%1,%2,%3}, {%4,%5,%6,%7}, {%8,%9}, {%0,%1,%2,%3};\n"
        : "+f"(c[0]), "+f"(c[1]), "+f"(c[2]), "+f"(c[3])
        : "r"(a0), "r"(a1), "r"(a2), "r"(a3), "r"(b0), "r"(b1));
}

// ---------------------------------------------------------------------------
// Kernel 0: round W to tf32 (RNA) once.
// ---------------------------------------------------------------------------
__global__ void wprep_kernel(const float* __restrict__ Wf) {
    int i = blockIdx.x * 512 + threadIdx.x;
    uint32_t u = f2tf32(Wf[i]);
    g_Wt[i] = __uint_as_float(u);
}

// ---------------------------------------------------------------------------
// Kernel 1: TF32 GEMM.  Y[r,n] = sum_k X[r,k]*W[n,k] + b[n]
// CTA tile 128(M) x 128(N), 256 threads = 8 warps (2M x 4N), warp tile 64x32.
// K staged 32 at a time, cp.async double-buffered, stride-36 smem
// (bank map (lane>>2)*4+(lane&3) == lane -> conflict-free fragments).
// Sized for 2 CTAs/SM (73.7KB smem, <=128 regs) so a co-resident CTA hides
// this CTA's barrier/staging bubbles, and attn CTAs fill ragged wave tails.
// ---------------------------------------------------------------------------
#define KSTG     32
#define STRIDE   36
#define OFF_A0   0
#define OFF_A1   (128 * STRIDE)              /* 4608  */
#define OFF_B0   (2 * 128 * STRIDE)          /* 9216  */
#define OFF_B1   (OFF_B0 + 128 * STRIDE)     /* 13824 */
#define SMEM_FLOATS (OFF_B1 + 128 * STRIDE)  /* 18432 floats = 73728 B */

__global__ __launch_bounds__(256, 2)
void gemm_tf32(const float* __restrict__ X, const float* __restrict__ bfc,
               int rowBase)
{
    extern __shared__ __align__(16) float smem[];

    const int tid  = threadIdx.x;
    const int lane = tid & 31;
    const int warp = tid >> 5;
    const int wm   = warp >> 2;          // 0..1 (M)
    const int wn   = warp & 3;           // 0..3 (N)
    const int row0 = rowBase + blockIdx.y * 128;
    const int col0 = blockIdx.x * 128;
    const uint32_t sbase = smem_u32(smem);

    float acc[4][4][4];
#pragma unroll
    for (int a = 0; a < 4; a++)
#pragma unroll
        for (int b = 0; b < 4; b++)
#pragma unroll
            for (int d = 0; d < 4; d++) acc[a][b][d] = 0.f;

    const float* Xc = X + (size_t)row0 * CDIM;
    const float* Wc = g_Wt + (size_t)col0 * CDIM;

    // per stage: A 128x32 = 1024 float4, B same; 4 each per thread
#define ISSUE_STAGE(IT, OFFA, OFFB)                                          \
    do {                                                                     \
        const int k0 = (IT) * KSTG;                                          \
        _Pragma("unroll")                                                    \
        for (int i = 0; i < 4; i++) {                                        \
            int f = i * 256 + tid;  /* 0..1023 */                            \
            int r = f >> 3, j = (f & 7) << 2;                                \
            cp16(sbase + ((OFFA) + r * STRIDE + j) * 4,                      \
                 Xc + (size_t)r * CDIM + k0 + j);                            \
        }                                                                    \
        _Pragma("unroll")                                                    \
        for (int i = 0; i < 4; i++) {                                        \
            int f = i * 256 + tid;                                           \
            int r = f >> 3, j = (f & 7) << 2;                                \
            cp16(sbase + ((OFFB) + r * STRIDE + j) * 4,                      \
                 Wc + (size_t)r * CDIM + k0 + j);                            \
        }                                                                    \
        asm volatile("cp.async.commit_group;" ::: "memory");                 \
    } while (0)

    ISSUE_STAGE(0, OFF_A0, OFF_B0);
    ISSUE_STAGE(1, OFF_A1, OFF_B1);

    const int ar = wm * 64 + (lane >> 2);
    const int ac = lane & 3;
    const int bn = wn * 32 + (lane >> 2);

    for (int it = 0; it < 16; it++) {
        if (it < 15) asm volatile("cp.async.wait_group 1;" ::: "memory");
        else         asm volatile("cp.async.wait_group 0;" ::: "memory");
        __syncthreads();

        const float*    sA = smem + ((it & 1) ? OFF_A1 : OFF_A0);
        const uint32_t* sB = (const uint32_t*)(smem + ((it & 1) ? OFF_B1 : OFF_B0));

#pragma unroll
        for (int kk = 0; kk < 4; kk++) {
            const int c = kk * 8 + ac;
            uint32_t b[4][2];
#pragma unroll
            for (int nt = 0; nt < 4; nt++) {
                b[nt][0] = sB[(bn + nt * 8) * STRIDE + c];
                b[nt][1] = sB[(bn + nt * 8) * STRIDE + c + 4];
            }
#pragma unroll
            for (int mt = 0; mt < 4; mt++) {
                const int r = ar + mt * 16;
                uint32_t a0 = f2tf32(sA[r * STRIDE + c]);
                uint32_t a1 = f2tf32(sA[(r + 8) * STRIDE + c]);
                uint32_t a2 = f2tf32(sA[r * STRIDE + c + 4]);
                uint32_t a3 = f2tf32(sA[(r + 8) * STRIDE + c + 4]);
#pragma unroll
                for (int nt = 0; nt < 4; nt++)
                    mma_tf32(acc[mt][nt], a0, a1, a2, a3, b[nt][0], b[nt][1]);
            }
        }
        __syncthreads();

        if (it < 14) {
            if (it & 1) ISSUE_STAGE(it + 2, OFF_A1, OFF_B1);
            else        ISSUE_STAGE(it + 2, OFF_A0, OFF_B0);
        }
    }

    // ---- epilogue: + bias, write fp32 Y ----
#pragma unroll
    for (int nt = 0; nt < 4; nt++) {
        const int c  = col0 + wn * 32 + nt * 8 + ((lane & 3) << 1);
        const float b0 = __ldg(bfc + c);
        const float b1 = __ldg(bfc + c + 1);
#pragma unroll
        for (int mt = 0; mt < 4; mt++) {
            const int r = row0 + wm * 64 + mt * 16 + (lane >> 2);
            float2 v0 = make_float2(acc[mt][nt][0] + b0, acc[mt][nt][1] + b1);
            float2 v1 = make_float2(acc[mt][nt][2] + b0, acc[mt][nt][3] + b1);
            *(float2*)&g_Y[(size_t)r * HID + c]       = v0;
            *(float2*)&g_Y[(size_t)(r + 8) * HID + c] = v1;
        }
    }
}

// ---------------------------------------------------------------------------
// Kernel 2a: syrk + double softmax.  One CTA (128 threads) per batch.
// Writes final P[b][81].
// ---------------------------------------------------------------------------
__global__ __launch_bounds__(128)
void syrk_kernel(int batch0)
{
    const int b    = batch0 + blockIdx.x;
    const int tid  = threadIdx.x;
    const int lane = tid & 31;
    const int warp = tid >> 5;

    __shared__ float sRed[4][45];
    __shared__ float sAttn[81];
    __shared__ float sB[81];

    const float* Yb = g_Y + (size_t)b * (HW81 * HID);

    float acc[45];
#pragma unroll
    for (int i = 0; i < 45; i++) acc[i] = 0.f;

#pragma unroll
    for (int cc = 0; cc < 2; cc++) {
        const int h = tid + cc * 128;
#pragma unroll
        for (int p = 0; p < 9; p++) {
            float z[9];
#pragma unroll
            for (int q = 0; q < 9; q++) {
                int rm = (3 * (q / 3) + p / 3) * 9 + 3 * (q % 3) + (p % 3);
                z[q] = Yb[rm * HID + h];
            }
            int cidx = 0;
#pragma unroll
            for (int n = 0; n < 9; n++)
#pragma unroll
                for (int m = n; m < 9; m++)
                    acc[cidx++] += z[n] * z[m];
        }
    }
#pragma unroll
    for (int i = 0; i < 45; i++) {
        float v = acc[i];
#pragma unroll
        for (int o = 16; o > 0; o >>= 1) v += __shfl_xor_sync(0xffffffffu, v, o);
        if (lane == 0) sRed[warp][i] = v;
    }
    __syncthreads();

    if (tid < 45) {
        float s = sRed[0][tid] + sRed[1][tid] + sRed[2][tid] + sRed[3][tid];
        int n = 0, m = tid;
        while (m >= 9 - n) { m -= (9 - n); n++; }
        m += n;
        float v = s * (1.0f / 48.0f);     // (hidden*P)^-0.5 = 1/sqrt(2304)
        if (n == m) v -= 100.0f;
        sAttn[n * 9 + m] = v;
        sAttn[m * 9 + n] = v;
    }
    __syncthreads();

    if (tid < 81) {
        int n = tid / 9, k = tid % 9;
        float s = 0.f;
#pragma unroll
        for (int m = 0; m < 9; m++) s += sAttn[n * 9 + m] * sAttn[k * 9 + m];
        sB[tid] = s * (1.0f / 3.0f);
    }
    __syncthreads();

    if (tid < 9) {
        int n = tid;
        float mx = -1e30f;
#pragma unroll
        for (int k = 0; k < 9; k++) mx = fmaxf(mx, sB[n * 9 + k]);
        float e[9]; float se = 0.f;
#pragma unroll
        for (int k = 0; k < 9; k++) { e[k] = expf(sB[n * 9 + k] - mx); se += e[k]; }
        float inv = 1.0f / se;
        float L[9]; float mx2 = -1e30f;
#pragma unroll
        for (int k = 0; k < 9; k++) {
            L[k] = sAttn[n * 9 + k] + e[k] * inv;
            mx2 = fmaxf(mx2, L[k]);
        }
        float e2[9]; float s2 = 0.f;
#pragma unroll
        for (int k = 0; k < 9; k++) { e2[k] = expf(L[k] - mx2); s2 += e2[k]; }
        float inv2 = 1.0f / s2;
#pragma unroll
        for (int k = 0; k < 9; k++) g_P[(size_t)b * HW81 + n * 9 + k] = e2[k] * inv2;
    }
}

// ---------------------------------------------------------------------------
// Kernel 2b: epilogue.  out[n,p,c] = sum_m P[n,m] * x[m,p,c].
// ---------------------------------------------------------------------------
__global__ __launch_bounds__(256)
void epi_kernel(const float* __restrict__ X, float* __restrict__ out, int batch0)
{
    const int b   = batch0 + blockIdx.x;
    const int tid = threadIdx.x;

    __shared__ float sP[81];
    if (tid < 81) sP[tid] = g_P[(size_t)b * HW81 + tid];
    __syncthreads();

    const float2* Xb = (const float2*)X + (size_t)b * (HW81 * 256);
    float2*       Ob = (float2*)out     + (size_t)b * (HW81 * 256);

#pragma unroll
    for (int p = 0; p < 9; p++) {
        float2 v[9];
#pragma unroll
        for (int m = 0; m < 9; m++) {
            int rm = (3 * (m / 3) + p / 3) * 9 + 3 * (m % 3) + (p % 3);
            v[m] = Xb[rm * 256 + tid];
        }
#pragma unroll
        for (int n = 0; n < 9; n++) {
            int rm = (3 * (n / 3) + p / 3) * 9 + 3 * (n % 3) + (p % 3);
            float2 o = make_float2(0.f, 0.f);
#pragma unroll
            for (int m = 0; m < 9; m++) {
                float w = sP[n * 9 + m];
                o.x += w * v[m].x;
                o.y += w * v[m].y;
            }
            Ob[rm * 256 + tid] = o;
        }
    }
}

// ---------------------------------------------------------------------------
extern "C" void kernel_launch(void* const* d_in, const int* in_sizes, int n_in,
                              void* d_out, int out_size)
{
    const float* x   = (const float*)d_in[0];   // [2048, 9, 9, 512] fp32
    const float* Wf  = (const float*)d_in[1];   // [256, 512] fp32
    const float* bfc = (const float*)d_in[2];   // [256] fp32
    float* out = (float*)d_out;

    static cudaStream_t s1 = nullptr;
    static cudaEvent_t  evG[NCHUNK], evJ;
    if (!s1) {
        cudaStreamCreateWithFlags(&s1, cudaStreamNonBlocking);
        for (int c = 0; c < NCHUNK; c++)
            cudaEventCreateWithFlags(&evG[c], cudaEventDisableTiming);
        cudaEventCreateWithFlags(&evJ, cudaEventDisableTiming);
        cudaFuncSetAttribute(gemm_tf32, cudaFuncAttributeMaxDynamicSharedMemorySize,
                             SMEM_FLOATS * 4);
    }

    // stream 0 (capture origin): wprep, then 4 gemm chunks, event after each
    wprep_kernel<<<256, 512>>>(Wf);
    for (int c = 0; c < NCHUNK; c++) {
        dim3 g1(HID / 128, RCHUNK / 128);        // (2, 324)
        gemm_tf32<<<g1, 256, SMEM_FLOATS * 4>>>(x, bfc, c * RCHUNK);
        cudaEventRecord(evG[c], 0);
    }

    // stream s1: per-chunk attention, gated on that chunk's gemm
    for (int c = 0; c < NCHUNK; c++) {
        cudaStreamWaitEvent(s1, evG[c], 0);
        syrk_kernel<<<BCHUNK, 128, 0, s1>>>(c * BCHUNK);
        epi_kernel<<<BCHUNK, 256, 0, s1>>>(x, out, c * BCHUNK);
    }

    // join back to the origin stream
    cudaEventRecord(evJ, s1);
    cudaStreamWaitEvent(0, evJ, 0);
}

// round 12
// speedup vs baseline: 1.1769x; 1.0613x over previous
#include <cuda_runtime.h>
#include <cuda_bf16.h>
#include <stdint.h>

#define BATCH 2048
#define HW81  81
#define CDIM  512
#define HID   256
#define MPAD  96                  /* 81 rows padded to 6x16 */

// W pre-rounded to tf32 (fp32 bit patterns), [256][512]
__device__ float g_Wt[HID * CDIM];

// ---------------------------------------------------------------------------
// helpers
// ---------------------------------------------------------------------------
__device__ __forceinline__ uint32_t f2tf32(float f) {
    uint32_t u;
    asm("cvt.rna.tf32.f32 %0, %1;" : "=r"(u) : "f"(f));
    return u;
}

__device__ __forceinline__ uint32_t smem_u32(const void* p) {
    uint32_t a;
    asm("{ .reg .u64 t; cvta.to.shared.u64 t, %1; cvt.u32.u64 %0, t; }" : "=r"(a) : "l"(p));
    return a;
}

__device__ __forceinline__ void cp16(uint32_t dst, const void* src) {
    asm volatile("cp.async.cg.shared.global [%0], [%1], 16;" :: "r"(dst), "l"(src));
}

__device__ __forceinline__ void mma_tf32(float* c, uint32_t a0, uint32_t a1,
                                         uint32_t a2, uint32_t a3,
                                         uint32_t b0, uint32_t b1) {
    asm volatile(
        "mma.sync.aligned.m16n8k8.row.col.f32.tf32.tf32.f32 "
        "{%0,%1,%2,%3}, {%4,%5,%6,%7}, {%8,%9}, {%0,%1,%2,%3};\n"
        : "+f"(c[0]), "+f"(c[1]), "+f"(c[2]), "+f"(c[3])
        : "r"(a0), "r"(a1), "r"(a2), "r"(a3), "r"(b0), "r"(b1));
}

// rm(q,p): row in x-natural order of token q of patch p's attention view
__device__ __forceinline__ int rowmap(int q, int p) {
    return (3 * (q / 3) + p / 3) * 9 + 3 * (q % 3) + (p % 3);
}

// ---------------------------------------------------------------------------
// Kernel 0: round W to tf32 (RNA) once.
// ---------------------------------------------------------------------------
__global__ void wprep_kernel(const float* __restrict__ Wf) {
    int i = blockIdx.x * 512 + threadIdx.x;
    g_Wt[i] = __uint_as_float(f2tf32(Wf[i]));
}

// ---------------------------------------------------------------------------
// Fused kernel: one CTA == one batch.
//   Phase 1 (GEMM): Y[96,256] = Xb(pad)[96,512] @ W^T + b  via tf32 mma.sync,
//     K staged 32 at a time, cp.async double-buffered, stride-36 smem.
//   Phase 2 (syrk+softmax): attn from smem-Y -> P[81] weights in smem.
//   Phase 3 (epilogue): out = P @ v, v = raw x pixels (L2-hot re-read).
// 256 threads = 8 warps (2M x 4N), warp tile 48x64, acc 96/thread.
// smem: staging 101376B dyn (Y 82944B reuses it), 2 CTAs/SM.
// ---------------------------------------------------------------------------
#define KSTG     32
#define STRIDE   36
#define OFF_A0   0
#define OFF_B0   (MPAD * STRIDE)                 /* 3456  */
#define OFF_A1   (OFF_B0 + HID * STRIDE)         /* 12672 */
#define OFF_B1   (OFF_A1 + MPAD * STRIDE)        /* 16128 */
#define SMEM_FLOATS (OFF_B1 + HID * STRIDE)      /* 25344 floats = 101376 B */

__global__ __launch_bounds__(256, 2)
void fused_kernel(const float* __restrict__ X, const float* __restrict__ bfc,
                  float* __restrict__ out)
{
    extern __shared__ __align__(16) float smem[];
    __shared__ float sBias[HID];
    __shared__ float sRed[8][45];
    __shared__ float sAttn[81];
    __shared__ float sB2[81];
    __shared__ float sP[81];

    const int b    = blockIdx.x;
    const int tid  = threadIdx.x;
    const int lane = tid & 31;
    const int warp = tid >> 5;
    const int wm   = warp >> 2;          // 0..1 (M)
    const int wn   = warp & 3;           // 0..3 (N)
    const uint32_t sbase = smem_u32(smem);

    const float* Xb = X + (size_t)b * (HW81 * CDIM);

    sBias[tid] = __ldg(bfc + tid);

    float acc[3][8][4];
#pragma unroll
    for (int a = 0; a < 3; a++)
#pragma unroll
        for (int c = 0; c < 8; c++)
#pragma unroll
            for (int d = 0; d < 4; d++) acc[a][c][d] = 0.f;

    // per stage: A 96x32 = 768 float4 (3/thread, rows>=81 clamp to 80),
    //            B 256x32 = 2048 float4 (8/thread)
#define ISSUE_STAGE(IT, OFFA, OFFB)                                          \
    do {                                                                     \
        const int k0 = (IT) * KSTG;                                          \
        _Pragma("unroll")                                                    \
        for (int i = 0; i < 3; i++) {                                        \
            int f = i * 256 + tid;  /* 0..767 */                             \
            int r = f >> 3, j = (f & 7) << 2;                                \
            int rs = r < HW81 ? r : (HW81 - 1);                              \
            cp16(sbase + ((OFFA) + r * STRIDE + j) * 4,                     \
                 Xb + (size_t)rs * CDIM + k0 + j);                          \
        }                                                                    \
        _Pragma("unroll")                                                    \
        for (int i = 0; i < 8; i++) {                                        \
            int f = i * 256 + tid;  /* 0..2047 */                            \
            int n = f >> 3, j = (f & 7) << 2;                                \
            cp16(sbase + ((OFFB) + n * STRIDE + j) * 4,                     \
                 g_Wt + (size_t)n * CDIM + k0 + j);                         \
        }                                                                    \
        asm volatile("cp.async.commit_group;" ::: "memory");                 \
    } while (0)

    ISSUE_STAGE(0, OFF_A0, OFF_B0);
    ISSUE_STAGE(1, OFF_A1, OFF_B1);

    const int ar = wm * 48 + (lane >> 2);
    const int ac = lane & 3;
    const int bn = wn * 64 + (lane >> 2);

    for (int it = 0; it < 16; it++) {
        if (it < 15) asm volatile("cp.async.wait_group 1;" ::: "memory");
        else         asm volatile("cp.async.wait_group 0;" ::: "memory");
        __syncthreads();

        const float*    sA = smem + ((it & 1) ? OFF_A1 : OFF_A0);
        const uint32_t* sB = (const uint32_t*)(smem + ((it & 1) ? OFF_B1 : OFF_B0));

#pragma unroll
        for (int kk = 0; kk < 4; kk++) {
            const int c = kk * 8 + ac;
            uint32_t bf[8][2];
#pragma unroll
            for (int nt = 0; nt < 8; nt++) {
                bf[nt][0] = sB[(bn + nt * 8) * STRIDE + c];
                bf[nt][1] = sB[(bn + nt * 8) * STRIDE + c + 4];
            }
#pragma unroll
            for (int mt = 0; mt < 3; mt++) {
                const int r = ar + mt * 16;
                uint32_t a0 = f2tf32(sA[r * STRIDE + c]);
                uint32_t a1 = f2tf32(sA[(r + 8) * STRIDE + c]);
                uint32_t a2 = f2tf32(sA[r * STRIDE + c + 4]);
                uint32_t a3 = f2tf32(sA[(r + 8) * STRIDE + c + 4]);
#pragma unroll
                for (int nt = 0; nt < 8; nt++)
                    mma_tf32(acc[mt][nt], a0, a1, a2, a3, bf[nt][0], bf[nt][1]);
            }
        }
        __syncthreads();

        if (it < 14) {
            if (it & 1) ISSUE_STAGE(it + 2, OFF_A1, OFF_B1);
            else        ISSUE_STAGE(it + 2, OFF_A0, OFF_B0);
        }
    }

    // ---- write Y (rows < 81 only) + bias into smem, reusing staging ----
    __syncthreads();           // all MMAs done reading stage buffers
    float* sY = smem;          // [81][256]
#pragma unroll
    for (int nt = 0; nt < 8; nt++) {
        const int cc = wn * 64 + nt * 8 + ((lane & 3) << 1);
        const float b0 = sBias[cc];
        const float b1 = sBias[cc + 1];
#pragma unroll
        for (int mt = 0; mt < 3; mt++) {
            const int r = ar + mt * 16;
            if (r < HW81) {
                sY[r * HID + cc]     = acc[mt][nt][0] + b0;
                sY[r * HID + cc + 1] = acc[mt][nt][1] + b1;
            }
            if (r + 8 < HW81) {
                sY[(r + 8) * HID + cc]     = acc[mt][nt][2] + b0;
                sY[(r + 8) * HID + cc + 1] = acc[mt][nt][3] + b1;
            }
        }
    }
    __syncthreads();

    // ---- syrk: attn[n,m] = (1/48) sum_{p,h} Y[rm(n,p),h] Y[rm(m,p),h] ----
    {
        float sa[45];
#pragma unroll
        for (int i = 0; i < 45; i++) sa[i] = 0.f;
#pragma unroll
        for (int p = 0; p < 9; p++) {
            float z[9];
#pragma unroll
            for (int q = 0; q < 9; q++)
                z[q] = sY[rowmap(q, p) * HID + tid];
            int cidx = 0;
#pragma unroll
            for (int n = 0; n < 9; n++)
#pragma unroll
                for (int m = n; m < 9; m++)
                    sa[cidx++] += z[n] * z[m];
        }
#pragma unroll
        for (int i = 0; i < 45; i++) {
            float v = sa[i];
#pragma unroll
            for (int o = 16; o > 0; o >>= 1) v += __shfl_xor_sync(0xffffffffu, v, o);
            if (lane == 0) sRed[warp][i] = v;
        }
    }
    __syncthreads();

    if (tid < 45) {
        float s = 0.f;
#pragma unroll
        for (int w = 0; w < 8; w++) s += sRed[w][tid];
        int n = 0, m = tid;
        while (m >= 9 - n) { m -= (9 - n); n++; }
        m += n;
        float v = s * (1.0f / 48.0f);     // (hidden*P)^-0.5 = 1/sqrt(2304)
        if (n == m) v -= 100.0f;          // diagonal self-suppression
        sAttn[n * 9 + m] = v;
        sAttn[m * 9 + n] = v;
    }
    __syncthreads();

    if (tid < 81) {
        int n = tid / 9, k = tid % 9;
        float s = 0.f;
#pragma unroll
        for (int m = 0; m < 9; m++) s += sAttn[n * 9 + m] * sAttn[k * 9 + m];
        sB2[tid] = s * (1.0f / 3.0f);
    }
    __syncthreads();

    if (tid < 9) {
        int n = tid;
        float mx = -1e30f;
#pragma unroll
        for (int k = 0; k < 9; k++) mx = fmaxf(mx, sB2[n * 9 + k]);
        float e[9]; float se = 0.f;
#pragma unroll
        for (int k = 0; k < 9; k++) { e[k] = expf(sB2[n * 9 + k] - mx); se += e[k]; }
        float inv = 1.0f / se;
        float L[9]; float mx2 = -1e30f;
#pragma unroll
        for (int k = 0; k < 9; k++) {
            L[k] = sAttn[n * 9 + k] + e[k] * inv;
            mx2 = fmaxf(mx2, L[k]);
        }
        float e2[9]; float s2 = 0.f;
#pragma unroll
        for (int k = 0; k < 9; k++) { e2[k] = expf(L[k] - mx2); s2 += e2[k]; }
        float inv2 = 1.0f / s2;
#pragma unroll
        for (int k = 0; k < 9; k++) sP[n * 9 + k] = e2[k] * inv2;
    }
    __syncthreads();

    // ---- epilogue: out[n,p,c] = sum_m P[n,m] * x[rm(m,p),c] ----
    const float2* Xb2 = (const float2*)Xb;                       // [81][256]
    float2*       Ob  = (float2*)out + (size_t)b * (HW81 * 256);

#pragma unroll
    for (int p = 0; p < 9; p++) {
        float2 v[9];
#pragma unroll
        for (int m = 0; m < 9; m++)
            v[m] = Xb2[rowmap(m, p) * 256 + tid];
#pragma unroll
        for (int n = 0; n < 9; n++) {
            float2 o = make_float2(0.f, 0.f);
#pragma unroll
            for (int m = 0; m < 9; m++) {
                float w = sP[n * 9 + m];
                o.x += w * v[m].x;
                o.y += w * v[m].y;
            }
            Ob[rowmap(n, p) * 256 + tid] = o;
        }
    }
}

// ---------------------------------------------------------------------------
extern "C" void kernel_launch(void* const* d_in, const int* in_sizes, int n_in,
                              void* d_out, int out_size)
{
    const float* x   = (const float*)d_in[0];   // [2048, 9, 9, 512] fp32
    const float* Wf  = (const float*)d_in[1];   // [256, 512] fp32
    const float* bfc = (const float*)d_in[2];   // [256] fp32
    float* out = (float*)d_out;

    static bool init = false;
    if (!init) {
        cudaFuncSetAttribute(fused_kernel,
                             cudaFuncAttributeMaxDynamicSharedMemorySize,
                             SMEM_FLOATS * 4);
        init = true;
    }

    wprep_kernel<<<256, 512>>>(Wf);
    fused_kernel<<<BATCH, 256, SMEM_FLOATS * 4>>>(x, bfc, out);
}